// round 11
// baseline (speedup 1.0000x reference)
#include <cuda_runtime.h>
#include <cstdint>
#include <math.h>

// Problem constants (fixed shapes)
#define N_ST   2048
#define N_OBS  8192
#define T_LEN  8192

#define N_BLOCKS     128
#define COLS_PER_CTA 16            // 2048 / 128
#define THREADS      256
#define KITER        16            // row-pairs per lane within the warp's 256-row window
#define GROUPS       8             // 8 warps <-> 8 row-groups of 256
#define CNT_STRIDE   16            // u64s between counters -> 128B (distinct L2 lines)

// ---- persistent device scratch (no allocations allowed) ----
__device__ float              g_Bobs[(size_t)T_LEN * N_ST];       // 64 MB
__device__ float              g_alpha[2][N_ST];                   // double-buffered alpha
__device__ unsigned long long g_cnt[GROUPS * CNT_STRIDE];         // group counters (reset at end)

// ---------------------------------------------------------------------------
// Sync + packed-f32x2 primitives
// ---------------------------------------------------------------------------
__device__ __forceinline__ unsigned long long ld_acquire_u64(const unsigned long long* p) {
    unsigned long long v;
    asm volatile("ld.acquire.gpu.global.u64 %0, [%1];" : "=l"(v) : "l"(p) : "memory");
    return v;
}
__device__ __forceinline__ void red_release_add_u64(unsigned long long* p, unsigned long long v) {
    asm volatile("red.release.gpu.global.add.u64 [%0], %1;" :: "l"(p), "l"(v) : "memory");
}
__device__ __forceinline__ unsigned long long pack_f32x2(float lo, float hi) {
    unsigned long long r;
    asm("mov.b64 %0, {%1, %2};" : "=l"(r) : "f"(lo), "f"(hi));
    return r;
}
__device__ __forceinline__ void unpack_f32x2(unsigned long long v, float& lo, float& hi) {
    asm("mov.b64 {%0, %1}, %2;" : "=f"(lo), "=f"(hi) : "l"(v));
}
__device__ __forceinline__ unsigned long long fma_f32x2(unsigned long long a,
                                                        unsigned long long b,
                                                        unsigned long long c) {
    unsigned long long d;
    asm("fma.rn.f32x2 %0, %1, %2, %3;" : "=l"(d) : "l"(a), "l"(b), "l"(c));
    return d;
}

// ---------------------------------------------------------------------------
// Kernel 1: gather emissions  Bobs[t][i] = B[i*N_OBS + se[t]]
// ---------------------------------------------------------------------------
__global__ void gather_bobs(const float* __restrict__ B, const int* __restrict__ se) {
    size_t idx    = (size_t)blockIdx.x * blockDim.x + threadIdx.x;
    size_t stride = (size_t)gridDim.x * blockDim.x;
    const size_t total = (size_t)T_LEN * N_ST;
    for (; idx < total; idx += stride) {
        int t = (int)(idx >> 11);
        int i = (int)(idx & (N_ST - 1));
        g_Bobs[idx] = B[(size_t)i * N_OBS + se[t]];
    }
}

// ---------------------------------------------------------------------------
// Kernel 2: persistent forward recursion, GROUP-DATAFLOW sync.
// CTA b owns output columns [16b, 16b+16). Warp w consumes alpha rows
// [256w, 256w+256), gated only by group counter w (16 producer CTAs).
// A-slice in registers as f32x2 row-pairs (R10-proven math).
// ---------------------------------------------------------------------------
__global__ void __launch_bounds__(THREADS, 1)
hmm_forward(const float* __restrict__ Pi0,
            const float* __restrict__ A,
            float* __restrict__ out)
{
    __shared__ __align__(16) float alpha_s[N_ST];   // warp-private 256-float windows
    __shared__ float red_s[2][GROUPS][COLS_PER_CTA];// double-buffered cross-warp partials

    const int tid     = threadIdx.x;
    const int b       = blockIdx.x;
    const int colbase = b * COLS_PER_CTA;
    const int lane    = tid & 31;
    const int warp    = tid >> 5;                   // == row group id
    const int c       = lane & 3;                   // 4-col group within 16
    const int q       = lane >> 2;                  // pair-stripe 0..7

    // ---- one-time: load A slice (rows of my warp window, my 4 cols) ----
    unsigned long long A2[KITER][4];
    #pragma unroll
    for (int k = 0; k < KITER; ++k) {
        int r0 = (warp << 8) + ((q + (k << 3)) << 1);          // rows r0, r0+1
        const float* p0 = A + (size_t)r0 * N_ST + colbase + (c << 2);
        float4 x0 = *(const float4*)p0;
        float4 x1 = *(const float4*)(p0 + N_ST);
        A2[k][0] = pack_f32x2(x0.x, x1.x);
        A2[k][1] = pack_f32x2(x0.y, x1.y);
        A2[k][2] = pack_f32x2(x0.z, x1.z);
        A2[k][3] = pack_f32x2(x0.w, x1.w);
    }

    // ---- step 0: alpha0 = Pi0 * Bobs[0], publish chunk, bump group counter ----
    if (warp == 0) {
        if (lane < COLS_PER_CTA) {
            int i = colbase + lane;
            __stcg(&g_alpha[0][i], Pi0[i] * g_Bobs[i]);
        }
        __syncwarp();
        if (lane == 0)
            red_release_add_u64(&g_cnt[(b >> 4) * CNT_STRIDE], 1ull);
    }

    // ---- steps 1 .. T-1 ----
    for (int t = 1; t < T_LEN; ++t) {
        // emission weights for publish (warp 0 only; independent of alpha)
        float bt = 0.0f;
        if (warp == 0 && lane < COLS_PER_CTA)
            bt = __ldg(&g_Bobs[(size_t)t * N_ST + colbase + lane]);

        // ---- wait ONLY for my row-group's 16 producers (steps 0..t-1 done) ----
        const unsigned long long tgt = (unsigned long long)t << 4;   // 16*t
        if (lane == 0) {
            while (ld_acquire_u64(&g_cnt[warp * CNT_STRIDE]) < tgt) { }
        }
        __syncwarp();

        // ---- stage my 256-row window (coalesced, conflict-free STS) ----
        {
            const float4* src = (const float4*)&g_alpha[(t - 1) & 1][warp << 8];
            float4 u0 = __ldcv(src + lane);
            float4 u1 = __ldcv(src + lane + 32);
            float4* dst = (float4*)&alpha_s[warp << 8];
            dst[lane]      = u0;
            dst[lane + 32] = u1;
        }
        __syncwarp();

        // ---- matvec partial over my window with packed f32x2 FMAs ----
        unsigned long long acc0 = 0ull, acc1 = 0ull, acc2 = 0ull, acc3 = 0ull;
        #pragma unroll
        for (int k = 0; k < KITER; ++k) {
            int p = q + (k << 3);
            unsigned long long a2 =
                *(const unsigned long long*)&alpha_s[(warp << 8) + (p << 1)]; // LDS.64
            acc0 = fma_f32x2(a2, A2[k][0], acc0);
            acc1 = fma_f32x2(a2, A2[k][1], acc1);
            acc2 = fma_f32x2(a2, A2[k][2], acc2);
            acc3 = fma_f32x2(a2, A2[k][3], acc3);
        }
        float s0, s1, s2, s3;
        {
            float lo, hi;
            unpack_f32x2(acc0, lo, hi); s0 = lo + hi;
            unpack_f32x2(acc1, lo, hi); s1 = lo + hi;
            unpack_f32x2(acc2, lo, hi); s2 = lo + hi;
            unpack_f32x2(acc3, lo, hi); s3 = lo + hi;
        }
        #pragma unroll
        for (int off = 4; off < 32; off <<= 1) {
            s0 += __shfl_xor_sync(0xffffffffu, s0, off);
            s1 += __shfl_xor_sync(0xffffffffu, s1, off);
            s2 += __shfl_xor_sync(0xffffffffu, s2, off);
            s3 += __shfl_xor_sync(0xffffffffu, s3, off);
        }
        if (lane < 4) {                  // lane == c here
            float* r = &red_s[t & 1][warp][lane << 2];
            r[0] = s0; r[1] = s1; r[2] = s2; r[3] = s3;
        }
        __syncthreads();                 // the ONLY full barrier per step

        // ---- warp 0: combine 8 warps' partials, apply emission, publish ----
        if (warp == 0) {
            if (lane < COLS_PER_CTA) {
                float sum = 0.f;
                #pragma unroll
                for (int w = 0; w < GROUPS; ++w) sum += red_s[t & 1][w][lane];
                __stcg(&g_alpha[t & 1][colbase + lane], sum * bt);
            }
            __syncwarp();
            if (lane == 0)
                red_release_add_u64(&g_cnt[(b >> 4) * CNT_STRIDE], 1ull);
        }
    }

    // ---- final reduction + counter reset by CTA 0 ----
    if (b == 0) {
        const unsigned long long tgt = (unsigned long long)T_LEN << 4;   // 16*T
        if (lane == 0) {
            while (ld_acquire_u64(&g_cnt[warp * CNT_STRIDE]) < tgt) { }
        }
        __syncthreads();

        const float4* s4 = (const float4*)g_alpha[(T_LEN - 1) & 1];
        float4 a0 = __ldcv(s4 + 2 * tid);
        float4 a1 = __ldcv(s4 + 2 * tid + 1);
        float ssum = a0.x + a0.y + a0.z + a0.w + a1.x + a1.y + a1.z + a1.w;
        #pragma unroll
        for (int off = 16; off > 0; off >>= 1)
            ssum += __shfl_xor_sync(0xffffffffu, ssum, off);
        if (lane == 0) red_s[0][warp][0] = ssum;
        __syncthreads();
        if (tid == 0) {
            float tot = 0.f;
            #pragma unroll
            for (int w = 0; w < GROUPS; ++w) tot += red_s[0][w][0];
            out[0] = -logf(tot);
            // reset counters for the next graph replay (all REDs observed above)
            #pragma unroll
            for (int g = 0; g < GROUPS; ++g)
                *((volatile unsigned long long*)&g_cnt[g * CNT_STRIDE]) = 0ull;
        }
    }
}

// ---------------------------------------------------------------------------
// Launch wrapper. Inputs (metadata order): Pi_0 [2048] f32, A [2048*2048] f32,
// B [2048*8192] f32, se [8192] i32. Output: 1 x f32.
// ---------------------------------------------------------------------------
extern "C" void kernel_launch(void* const* d_in, const int* in_sizes, int n_in,
                              void* d_out, int out_size) {
    const float* Pi0 = (const float*)d_in[0];
    const float* A   = (const float*)d_in[1];
    const float* B   = (const float*)d_in[2];
    const int*   se  = (const int*)d_in[3];
    float*       out = (float*)d_out;

    (void)in_sizes; (void)n_in; (void)out_size;

    gather_bobs<<<2048, 256>>>(B, se);
    hmm_forward<<<N_BLOCKS, THREADS>>>(Pi0, A, out);
}

// round 12
// speedup vs baseline: 2.0722x; 2.0722x over previous
#include <cuda_runtime.h>
#include <cstdint>
#include <math.h>

// Problem constants (fixed shapes)
#define N_ST   2048
#define N_OBS  8192
#define T_LEN  8192

#define N_BLOCKS     128
#define COLS_PER_CTA 16            // 2048 / 128
#define THREADS      256
#define GROUPS       8             // 8 warps <-> 8 row-windows of 256
#define KITER        16            // row-pairs per lane within the warp's window

// ---- persistent device scratch (no allocations allowed) ----
__device__ float              g_Bobs[(size_t)T_LEN * N_ST];   // 64 MB
__device__ float              g_alpha[2][N_ST];               // double-buffered alpha
__device__ unsigned long long g_count;                        // aggregated step counter

// ---------------------------------------------------------------------------
// Sync + packed-f32x2 primitives
// ---------------------------------------------------------------------------
__device__ __forceinline__ unsigned long long ld_relaxed_u64(const unsigned long long* p) {
    unsigned long long v;
    asm volatile("ld.relaxed.gpu.global.u64 %0, [%1];" : "=l"(v) : "l"(p) : "memory");
    return v;
}
__device__ __forceinline__ void fence_acquire_gpu() {
    asm volatile("fence.acquire.gpu;" ::: "memory");
}
__device__ __forceinline__ void red_release_add_u64(unsigned long long* p, unsigned long long v) {
    asm volatile("red.release.gpu.global.add.u64 [%0], %1;" :: "l"(p), "l"(v) : "memory");
}
__device__ __forceinline__ unsigned long long pack_f32x2(float lo, float hi) {
    unsigned long long r;
    asm("mov.b64 %0, {%1, %2};" : "=l"(r) : "f"(lo), "f"(hi));
    return r;
}
__device__ __forceinline__ void unpack_f32x2(unsigned long long v, float& lo, float& hi) {
    asm("mov.b64 {%0, %1}, %2;" : "=f"(lo), "=f"(hi) : "l"(v));
}
__device__ __forceinline__ unsigned long long fma_f32x2(unsigned long long a,
                                                        unsigned long long b,
                                                        unsigned long long c) {
    unsigned long long d;
    asm("fma.rn.f32x2 %0, %1, %2, %3;" : "=l"(d) : "l"(a), "l"(b), "l"(c));
    return d;
}

// ---------------------------------------------------------------------------
// Kernel 1: gather emissions  Bobs[t][i] = B[i*N_OBS + se[t]]
// ---------------------------------------------------------------------------
__global__ void gather_bobs(const float* __restrict__ B, const int* __restrict__ se) {
    size_t idx    = (size_t)blockIdx.x * blockDim.x + threadIdx.x;
    size_t stride = (size_t)gridDim.x * blockDim.x;
    const size_t total = (size_t)T_LEN * N_ST;
    for (; idx < total; idx += stride) {
        int t = (int)(idx >> 11);
        int i = (int)(idx & (N_ST - 1));
        g_Bobs[idx] = B[(size_t)i * N_OBS + se[t]];
    }
}

// ---------------------------------------------------------------------------
// Kernel 2: persistent forward recursion (R10 sync skeleton, 2 barriers/step).
// CTA b owns output columns [16b, 16b+16). Warp w owns alpha rows
// [256w, 256w+256): it stages ONLY its window (syncwarp) and FMAs over it.
// Cross-warp column combine in warp 0 after the single pre-combine barrier.
// ---------------------------------------------------------------------------
__global__ void __launch_bounds__(THREADS, 1)
hmm_forward(const float* __restrict__ Pi0,
            const float* __restrict__ A,
            float* __restrict__ out)
{
    __shared__ __align__(16) float alpha_s[N_ST];      // 8 warp-private windows
    __shared__ float red_s[GROUPS][COLS_PER_CTA];      // per-warp column partials

    const int tid     = threadIdx.x;
    const int b       = blockIdx.x;
    const int colbase = b * COLS_PER_CTA;
    const int lane    = tid & 31;
    const int warp    = tid >> 5;                      // row-window id
    const int c       = lane & 3;                      // 4-col group within 16
    const int q       = lane >> 2;                     // pair-stripe 0..7

    // ---- one-time: load A slice for my window as f32x2 row-pairs ----
    unsigned long long A2[KITER][4];
    #pragma unroll
    for (int k = 0; k < KITER; ++k) {
        int r0 = (warp << 8) + ((q + (k << 3)) << 1);  // rows r0, r0+1 (global)
        const float* p0 = A + (size_t)r0 * N_ST + colbase + (c << 2);
        float4 x0 = *(const float4*)p0;
        float4 x1 = *(const float4*)(p0 + N_ST);
        A2[k][0] = pack_f32x2(x0.x, x1.x);
        A2[k][1] = pack_f32x2(x0.y, x1.y);
        A2[k][2] = pack_f32x2(x0.z, x1.z);
        A2[k][3] = pack_f32x2(x0.w, x1.w);
    }

    // ---- step 0: alpha0 = Pi0 * Bobs[0] (warp 0 publishes, then REDs) ----
    if (warp == 0) {
        if (lane < COLS_PER_CTA) {
            int i = colbase + lane;
            __stcg(&g_alpha[0][i], Pi0[i] * g_Bobs[i]);
        }
        __syncwarp();
        if (lane == 0) red_release_add_u64(&g_count, 1ull);
    }

    // ---- steps 1 .. T-1 ----
    for (int t = 1; t < T_LEN; ++t) {
        // emission weights for publish (warp 0; independent of alpha)
        float bt = 0.0f;
        if (warp == 0 && lane < COLS_PER_CTA)
            bt = __ldg(&g_Bobs[(size_t)t * N_ST + colbase + lane]);

        // ---- single poller on the single counter (proven topology) ----
        const unsigned long long tgt = (unsigned long long)t << 7;   // 128*t
        if (tid == 0) {
            while (ld_relaxed_u64(&g_count) < tgt) { }
            fence_acquire_gpu();
        }
        __syncthreads();                                // barrier 1

        // ---- per-warp stage of MY 256-row window (no CTA barrier) ----
        {
            const float4* src = (const float4*)&g_alpha[(t - 1) & 1][warp << 8];
            float4 u0 = __ldcv(src + lane);
            float4 u1 = __ldcv(src + lane + 32);
            float4* dst = (float4*)&alpha_s[warp << 8];
            dst[lane]      = u0;
            dst[lane + 32] = u1;
        }
        __syncwarp();

        // ---- matvec partial over my window (packed f32x2) ----
        unsigned long long acc0 = 0ull, acc1 = 0ull, acc2 = 0ull, acc3 = 0ull;
        #pragma unroll
        for (int k = 0; k < KITER; ++k) {
            unsigned long long a2 = *(const unsigned long long*)
                &alpha_s[(warp << 8) + ((q + (k << 3)) << 1)];       // LDS.64
            acc0 = fma_f32x2(a2, A2[k][0], acc0);
            acc1 = fma_f32x2(a2, A2[k][1], acc1);
            acc2 = fma_f32x2(a2, A2[k][2], acc2);
            acc3 = fma_f32x2(a2, A2[k][3], acc3);
        }
        float s0, s1, s2, s3;
        {
            float lo, hi;
            unpack_f32x2(acc0, lo, hi); s0 = lo + hi;
            unpack_f32x2(acc1, lo, hi); s1 = lo + hi;
            unpack_f32x2(acc2, lo, hi); s2 = lo + hi;
            unpack_f32x2(acc3, lo, hi); s3 = lo + hi;
        }
        #pragma unroll
        for (int off = 4; off < 32; off <<= 1) {        // reduce over q
            s0 += __shfl_xor_sync(0xffffffffu, s0, off);
            s1 += __shfl_xor_sync(0xffffffffu, s1, off);
            s2 += __shfl_xor_sync(0xffffffffu, s2, off);
            s3 += __shfl_xor_sync(0xffffffffu, s3, off);
        }
        if (lane < 4) {                                 // lane == c here
            float* r = &red_s[warp][lane << 2];
            r[0] = s0; r[1] = s1; r[2] = s2; r[3] = s3;
        }
        __syncthreads();                                // barrier 2

        // ---- warp 0: combine, apply emission, publish, bump counter ----
        if (warp == 0) {
            if (lane < COLS_PER_CTA) {
                float sum = 0.f;
                #pragma unroll
                for (int w = 0; w < GROUPS; ++w) sum += red_s[w][lane];
                __stcg(&g_alpha[t & 1][colbase + lane], sum * bt);
            }
            __syncwarp();
            if (lane == 0) red_release_add_u64(&g_count, 1ull);
        }
        // red_s reuse is ordered by barrier 1 of step t+1 (warp0's reads
        // happen before it; all STS of t+1 happen after it).
    }

    // ---- final reduction + counter reset by CTA 0 ----
    if (b == 0) {
        const unsigned long long tgt = (unsigned long long)T_LEN << 7;
        if (tid == 0) {
            while (ld_relaxed_u64(&g_count) < tgt) { }
            fence_acquire_gpu();
        }
        __syncthreads();

        const float4* s4 = (const float4*)g_alpha[(T_LEN - 1) & 1];
        float4 a0 = __ldcv(s4 + 2 * tid);
        float4 a1 = __ldcv(s4 + 2 * tid + 1);
        float ssum = a0.x + a0.y + a0.z + a0.w + a1.x + a1.y + a1.z + a1.w;
        #pragma unroll
        for (int off = 16; off > 0; off >>= 1)
            ssum += __shfl_xor_sync(0xffffffffu, ssum, off);
        if (lane == 0) red_s[warp][0] = ssum;
        __syncthreads();
        if (tid == 0) {
            float tot = 0.f;
            #pragma unroll
            for (int w = 0; w < GROUPS; ++w) tot += red_s[w][0];
            out[0] = -logf(tot);
            // reset counter for next graph replay (all REDs observed above)
            *((volatile unsigned long long*)&g_count) = 0ull;
        }
    }
}

// ---------------------------------------------------------------------------
// Launch wrapper. Inputs (metadata order): Pi_0 [2048] f32, A [2048*2048] f32,
// B [2048*8192] f32, se [8192] i32. Output: 1 x f32.
// ---------------------------------------------------------------------------
extern "C" void kernel_launch(void* const* d_in, const int* in_sizes, int n_in,
                              void* d_out, int out_size) {
    const float* Pi0 = (const float*)d_in[0];
    const float* A   = (const float*)d_in[1];
    const float* B   = (const float*)d_in[2];
    const int*   se  = (const int*)d_in[3];
    float*       out = (float*)d_out;

    (void)in_sizes; (void)n_in; (void)out_size;

    gather_bobs<<<2048, 256>>>(B, se);
    hmm_forward<<<N_BLOCKS, THREADS>>>(Pi0, A, out);
}